// round 16
// baseline (speedup 1.0000x reference)
#include <cuda_runtime.h>
#include <math.h>
#include <stdint.h>

// Problem constants
#define U      128
#define NC     10
#define NF     3
#define TT     1000
#define BB     256
#define CSZ    4              // CTAs per cluster
#define GC     8              // batch elements per cluster
#define OWN    32             // units owned per CTA
#define NTHR   512            // group A (0-255) recurrence path, group B (256-511) off-path
#define NCTA   128            // (BB/GC)*CSZ
#define HR     132            // h row stride in floats ([b][u] layout, bank-skewed, 16B-mult)

#define R_ON_   0.05f
#define ALPHA_  0.001f
#define LN_EPS_ 1e-3f

// ---- packed f32x2 helpers (FFMA2: 2x fp32 MAC throughput) ----
__device__ __forceinline__ unsigned long long pack2(float a, float b) {
    unsigned long long r;
    asm("mov.b64 %0, {%1, %2};" : "=l"(r) : "f"(a), "f"(b));
    return r;
}
__device__ __forceinline__ void fma2p(unsigned long long& acc,
                                      unsigned long long a,
                                      unsigned long long b) {
    asm("fma.rn.f32x2 %0, %1, %2, %0;" : "+l"(acc) : "l"(a), "l"(b));
}

// ---- fast transcendental helpers (rel err ~1e-6, budget is 1e-3) ----
__device__ __forceinline__ float fsig(float x) {
    return __fdividef(1.0f, 1.0f + __expf(-x));
}
__device__ __forceinline__ float ftanh(float x) {
    float ax = fabsf(x);
    float e  = __expf(-2.0f * ax);
    float t  = __fdividef(1.0f - e, 1.0f + e);
    return copysignf(t, x);
}

// hardware cluster barrier (all threads of all 4 CTAs; subsumes __syncthreads)
#define CLUSTER_SYNC() do { \
    asm volatile("barrier.cluster.arrive.aligned;" ::: "memory"); \
    asm volatile("barrier.cluster.wait.aligned;"   ::: "memory"); } while (0)

// ---- DSMEM stores (packed) ----
__device__ __forceinline__ void stc_v2(uint32_t la, uint32_t r, float a, float b) {
    uint32_t ra;
    asm volatile("mapa.shared::cluster.u32 %0, %1, %2;" : "=r"(ra) : "r"(la), "r"(r));
    asm volatile("st.shared::cluster.v2.f32 [%0], {%1, %2};"
                 :: "r"(ra), "f"(a), "f"(b) : "memory");
}
__device__ __forceinline__ void stc_v4(uint32_t la, uint32_t r,
                                       float a, float b, float c, float d) {
    uint32_t ra;
    asm volatile("mapa.shared::cluster.u32 %0, %1, %2;" : "=r"(ra) : "r"(la), "r"(r));
    asm volatile("st.shared::cluster.v4.f32 [%0], {%1, %2, %3, %4};"
                 :: "r"(ra), "f"(a), "f"(b), "f"(c), "f"(d) : "memory");
}

// Dynamic SMEM: 58080 floats = 232320 B (<= 232448 B limit, 1 CTA/SM)
struct __align__(16) SM {
    float Wh0s[128 * 128];      // own 128 cols (gate-interleaved) of Wh0, plain [k][lc]
    float Wx1g[128 * 128];      // own cols of Wx1 * gamma[k]
    float Wh1s[128 * 128];
    float z0[2 * 8 * 128];      // layer-0 pre-activations [ks][b][lc]
    float z1[2 * 8 * 128];      // layer-1 pre-activations (pre-fold + fold)
    float h0f[GC * HR];         // h0, [b*HR + unit], single-buffered
    float h1f[GC * HR];         // h1, same layout
    float hs[2 * 128];          // snapshot of h1(t-1) for this CTA's 2 batches
    float Wx0s[4 * 128];        // own cols of Wx0 [f][lc]; row 3 = b0 (x3 == 1)
    float S1cs[2][128];         // per-slab col sums of Wx1g
    float S2cs[2][128];         // per-slab col sums of Wx1*beta (+ b1 on slab 0)
    float WfcT[NC * 128];       // Wfc transposed: [c][u]
    float bfcs[16];
    float2 red2[CSZ * GC];      // LN partials {sum, sumsq} [srcRank*8 + b]
    float xb[2][GC][4];         // double-buffered inputs (f padded; [3] == 1.0f)
    float tmb[2][GC];           // double-buffered times
};

// One 64-row K-slab: 4 cols (quad) x 2 batches (bpair) per thread.
__device__ __forceinline__ void mv2(const float* __restrict__ Ws,
                                    const float* __restrict__ hb0,
                                    int kbase, int quad,
                                    unsigned long long acc[2][2]) {
    const ulonglong2* w2 = reinterpret_cast<const ulonglong2*>(Ws + kbase * 128) + quad;
    const float* h0p = hb0 + kbase;          // batch 2bp
    const float* h1p = hb0 + HR + kbase;     // batch 2bp+1
    #pragma unroll 8
    for (int k4 = 0; k4 < 16; ++k4) {
        float4 ha = *reinterpret_cast<const float4*>(h0p + 4 * k4);
        float4 hb = *reinterpret_cast<const float4*>(h1p + 4 * k4);
        float hav[4] = {ha.x, ha.y, ha.z, ha.w};
        float hbv[4] = {hb.x, hb.y, hb.z, hb.w};
        #pragma unroll
        for (int j = 0; j < 4; ++j) {
            ulonglong2 w = w2[(4 * k4 + j) * 32];
            unsigned long long hd0 = pack2(hav[j], hav[j]);
            unsigned long long hd1 = pack2(hbv[j], hbv[j]);
            fma2p(acc[0][0], w.x, hd0); fma2p(acc[1][0], w.y, hd0);
            fma2p(acc[0][1], w.x, hd1); fma2p(acc[1][1], w.y, hd1);
        }
    }
}

// PhasedLSTM gate + time gate (fast mod via reciprocal + clamps; q < 1000 << 2^24)
__device__ __forceinline__ void plstm_gate2(float zi, float zf, float zg, float zo,
                                            float tcur, float tau, float itau, float s,
                                            float& h, float& c) {
    float ch = fsig(zf) * c + fsig(zi) * ftanh(zg);
    float hh = fsig(zo) * ftanh(ch);
    float d = tcur - s;
    float q = truncf(d * itau);
    float m = fmaf(-q, tau, d);
    m = (m < 0.0f)  ? m + tau : m;
    m = (m >= tau)  ? m - tau : m;
    m = (m < 0.0f)  ? m + tau : m;
    float phi = m * itau;
    float kg;
    if (phi < 0.5f * R_ON_)      kg = (2.0f * phi) / R_ON_;
    else if (phi < R_ON_)        kg = 2.0f - (2.0f * phi) / R_ON_;
    else                         kg = ALPHA_ * phi;
    h = kg * hh + (1.0f - kg) * h;
    c = kg * ch + (1.0f - kg) * c;
}

// Local FC + softmax for one batch's 10 classes (whole warp converged).
// hsrc = 128 floats of h1 for this batch; writes out[orow*NC + c].
__device__ __forceinline__ void fc_softmax(const float* __restrict__ hsrc,
                                           const float* __restrict__ WfcT,
                                           const float* __restrict__ bfcs,
                                           float* __restrict__ outp, int lane) {
    int c2 = lane >> 1, half = lane & 1;
    bool valid = (c2 < NC);
    int cc = valid ? c2 : NC - 1;            // clamp for safe loads
    const float4* wp = reinterpret_cast<const float4*>(WfcT + cc * 128 + half * 64);
    const float4* hp = reinterpret_cast<const float4*>(hsrc + half * 64);
    float a = 0.0f;
    #pragma unroll
    for (int i = 0; i < 16; ++i) {
        float4 w = wp[i], h = hp[i];
        a = fmaf(w.x, h.x, a); a = fmaf(w.y, h.y, a);
        a = fmaf(w.z, h.z, a); a = fmaf(w.w, h.w, a);
    }
    a += __shfl_xor_sync(0xffffffffu, a, 1);     // merge halves
    float lg = valid ? (a + bfcs[cc]) : -1e30f;
    float mx = lg;
    #pragma unroll
    for (int o = 2; o < 32; o <<= 1)
        mx = fmaxf(mx, __shfl_xor_sync(0xffffffffu, mx, o));
    float e = valid ? __expf(lg - mx) : 0.0f;
    float ssum = e;
    #pragma unroll
    for (int o = 2; o < 32; o <<= 1)
        ssum += __shfl_xor_sync(0xffffffffu, ssum, o);
    if (valid && half == 0)
        outp[c2] = e * __fdividef(1.0f, ssum);
}

__global__ void __launch_bounds__(NTHR, 1) __cluster_dims__(CSZ, 1, 1)
plstm_cluster_kernel(const float* __restrict__ inputs, const float* __restrict__ times,
                     const float* __restrict__ gWx0, const float* __restrict__ gWh0,
                     const float* __restrict__ gb0,  const float* __restrict__ gtau0,
                     const float* __restrict__ gs0,  const float* __restrict__ gWx1,
                     const float* __restrict__ gWh1, const float* __restrict__ gb1,
                     const float* __restrict__ gtau1,const float* __restrict__ gs1,
                     const float* __restrict__ ggamma,const float* __restrict__ gbeta,
                     const float* __restrict__ gWfc, const float* __restrict__ gbfc,
                     float* __restrict__ out) {
    extern __shared__ float smraw[];
    SM& sm = *reinterpret_cast<SM*>(smraw);
    const int tid = threadIdx.x;
    uint32_t rank;
    asm("mov.u32 %0, %%cluster_ctarank;" : "=r"(rank));
    const int bstart = (blockIdx.x >> 2) * GC;

    const bool isA = (tid < 256);
    const int mt    = tid & 255;
    const int ks    = mt >> 7;
    const int mlane = mt & 31;
    const int wq    = (mt >> 5) & 3;
    const int bp    = mlane >> 3;
    const int quad  = wq * 8 + (mlane & 7);
    const int kbase = ks << 6;
    const int lcq   = quad * 4;
    // gate mapping (A): warp gb = batch, lane gj = own unit
    const int gb = tid >> 5, gj = tid & 31;

    // ---- one-time SMEM setup ----
    for (int i = tid; i < 128 * 128; i += NTHR) {
        int k = i >> 7, c = i & 127;
        int gcol = ((c >> 5) << 7) + ((int)rank << 5) + (c & 31);
        sm.Wh0s[i] = gWh0[k * 512 + gcol];
        sm.Wx1g[i] = gWx1[k * 512 + gcol];   // raw; scaled by gamma below
        sm.Wh1s[i] = gWh1[k * 512 + gcol];
    }
    for (int i = tid; i < 4 * 128; i += NTHR) {
        int f = i >> 7, c = i & 127;
        int gcol = ((c >> 5) << 7) + ((int)rank << 5) + (c & 31);
        sm.Wx0s[i] = (f < NF) ? gWx0[f * 512 + gcol] : gb0[gcol];  // row 3 = b0
    }
    // per-lane gate constants -> registers (A threads)
    float rtau0 = 0.f, rs0 = 0.f, ritau0 = 0.f, rtau1 = 0.f, rs1 = 0.f, ritau1 = 0.f;
    if (isA) {
        int u = (int)rank * OWN + gj;
        rtau0 = gtau0[u]; rs0 = gs0[u]; ritau0 = 1.0f / rtau0;
        rtau1 = gtau1[u]; rs1 = gs1[u]; ritau1 = 1.0f / rtau1;
    }
    for (int i = tid; i < NC * 128; i += NTHR) {
        int c = i >> 7, u = i & 127;
        sm.WfcT[i] = gWfc[u * NC + c];
    }
    if (tid < NC) sm.bfcs[tid] = gbfc[tid];
    for (int i = tid; i < GC * HR; i += NTHR) { sm.h0f[i] = 0.0f; sm.h1f[i] = 0.0f; }
    for (int i = tid; i < 2 * 128; i += NTHR) sm.hs[i] = 0.0f;
    if (tid < GC) {
        sm.tmb[0][tid] = times[(size_t)(bstart + tid) * TT];
        sm.tmb[1][tid] = times[(size_t)(bstart + tid) * TT + 1];
    }
    if (tid < 2 * GC) {
        int bfr = tid >> 3, g = tid & 7;
        sm.xb[bfr][g][3] = 1.0f;             // bias multiplier
    }
    if (tid < GC * NF) {
        int g = tid / NF, f = tid - g * NF;
        sm.xb[0][g][f] = inputs[((size_t)(bstart + g) * TT) * NF + f];
        sm.xb[1][g][f] = inputs[((size_t)(bstart + g) * TT + 1) * NF + f];
    }
    __syncthreads();

    if (isA) {
        // Wx1g *= gamma[k]; per-slab col sums S1 (Wx1*gm), S2 (Wx1*bt + b1 on slab 0)
        const int lc = tid & 127;
        float s1 = 0.0f, s2 = 0.0f;
        for (int k = 0; k < 64; ++k) {
            int kk = kbase + k;
            int ni = kk * 128 + lc;
            float w = sm.Wx1g[ni];
            float wg = w * ggamma[kk];
            sm.Wx1g[ni] = wg;
            s1 += wg;
            s2 += w * gbeta[kk];
        }
        int gcol = ((lc >> 5) << 7) + ((int)rank << 5) + (lc & 31);
        sm.S1cs[ks][lc] = s1;
        sm.S2cs[ks][lc] = s2 + (ks == 0 ? gb1[gcol] : 0.0f);
    } else {
        // pre-loop z0(0) = x(0)@Wx0 + b0 (h0 = 0); b0 is Wx0 row 3, x3 == 1
        float* zp = sm.z0 + ks * 1024 + (2 * bp) * 128 + lcq;
        if (ks == 0) {
            float4 w0v = *reinterpret_cast<const float4*>(&sm.Wx0s[lcq]);
            float4 w1v = *reinterpret_cast<const float4*>(&sm.Wx0s[128 + lcq]);
            float4 w2v = *reinterpret_cast<const float4*>(&sm.Wx0s[256 + lcq]);
            float4 w3v = *reinterpret_cast<const float4*>(&sm.Wx0s[384 + lcq]);
            #pragma unroll
            for (int d = 0; d < 2; ++d) {
                const float* x = sm.xb[0][2 * bp + d];
                float xa = x[0], xb_ = x[1], xc = x[2];
                zp[d * 128 + 0] = w3v.x + xa * w0v.x + xb_ * w1v.x + xc * w2v.x;
                zp[d * 128 + 1] = w3v.y + xa * w0v.y + xb_ * w1v.y + xc * w2v.y;
                zp[d * 128 + 2] = w3v.z + xa * w0v.z + xb_ * w1v.z + xc * w2v.z;
                zp[d * 128 + 3] = w3v.w + xa * w0v.w + xb_ * w1v.w + xc * w2v.w;
            }
        } else {
            #pragma unroll
            for (int d = 0; d < 2; ++d) {
                zp[d * 128 + 0] = 0.0f; zp[d * 128 + 1] = 0.0f;
                zp[d * 128 + 2] = 0.0f; zp[d * 128 + 3] = 0.0f;
            }
        }
    }
    CLUSTER_SYNC();   // all CTAs initialized before any remote traffic

    float* const zp0 = sm.z0 + ks * 1024 + (2 * bp) * 128 + lcq;
    float* const zp1 = sm.z1 + ks * 1024 + (2 * bp) * 128 + lcq;
    // A-thread persistent own state (unit u = rank*32+gj, batch gb)
    float h0own = 0.0f, c0own = 0.0f, h1own = 0.0f, c1own = 0.0f;
    const int packsrc = (gj & 7) * 4;       // lane source base for packed exchange
    const uint32_t dstrank = (uint32_t)(gj >> 3);
    const int w8 = (tid >> 5) - 8;          // B softmax warp index (0/1 for warps 8/9)

    for (int t = 0; t < TT; ++t) {
        const int par = t & 1, parn = par ^ 1;
        float tcur = 0.0f;

        // ===== P1: A: gates0 + packed h0 exchange + LN partials
        //          B: snapshot h1(t-1) (warps 8/9) + Wh1@h1(t-1) -> z1 =====
        if (isA) {
            const float* zb = sm.z0 + gb * 128;
            float zi = zb[gj]      + zb[1024 + gj];
            float zf = zb[32 + gj] + zb[1024 + 32 + gj];
            float zg = zb[64 + gj] + zb[1024 + 64 + gj];
            float zo = zb[96 + gj] + zb[1024 + 96 + gj];
            tcur = sm.tmb[par][gb];
            plstm_gate2(zi, zf, zg, zo, tcur, rtau0, ritau0, rs0, h0own, c0own);
            // packed exchange: lane group (gj>>3) ships 32 own units as v4 to rank gj>>3
            float v0 = __shfl_sync(0xffffffffu, h0own, packsrc + 0);
            float v1 = __shfl_sync(0xffffffffu, h0own, packsrc + 1);
            float v2 = __shfl_sync(0xffffffffu, h0own, packsrc + 2);
            float v3 = __shfl_sync(0xffffffffu, h0own, packsrc + 3);
            uint32_t la = (uint32_t)__cvta_generic_to_shared(
                &sm.h0f[gb * HR + (int)rank * OWN + packsrc]);
            stc_v4(la, dstrank, v0, v1, v2, v3);
            float s = h0own, q = h0own * h0own;
            #pragma unroll
            for (int o = 16; o; o >>= 1) {
                s += __shfl_xor_sync(0xffffffffu, s, o);
                q += __shfl_xor_sync(0xffffffffu, q, o);
            }
            if (gj < 4) {
                uint32_t lr = (uint32_t)__cvta_generic_to_shared(
                    &sm.red2[(int)rank * GC + gb]);
                stc_v2(lr, (uint32_t)gj, s, q);
            }
        } else {
            // snapshot h1(t-1) for own 2 batches (stable: no remote P3(t) before S1)
            if (w8 < 2) {
                int bown = (int)rank * 2 + w8;
                *reinterpret_cast<float4*>(&sm.hs[w8 * 128 + (tid & 31) * 4]) =
                    *reinterpret_cast<const float4*>(&sm.h1f[bown * HR + (tid & 31) * 4]);
            }
            unsigned long long accW[2][2];
            float4 s2v = *reinterpret_cast<const float4*>(&sm.S2cs[ks][lcq]);
            accW[0][0] = pack2(s2v.x, s2v.y); accW[1][0] = pack2(s2v.z, s2v.w);
            accW[0][1] = accW[0][0];          accW[1][1] = accW[1][0];
            mv2(sm.Wh1s, &sm.h1f[(2 * bp) * HR], kbase, quad, accW);
            *reinterpret_cast<unsigned long long*>(zp1)       = accW[0][0];
            *reinterpret_cast<unsigned long long*>(zp1 + 2)   = accW[1][0];
            *reinterpret_cast<unsigned long long*>(zp1 + 128) = accW[0][1];
            *reinterpret_cast<unsigned long long*>(zp1 + 130) = accW[1][1];
        }
        CLUSTER_SYNC();        // S1: h0(t), LN partials, z1 pre-fold visible

        // ===== P2: A: Wx1g@h0 + LN fold -> z1
        //          B: softmax(t-1) (warps 8/9), x/t prefetch, next z0 =====
        if (isA) {
            unsigned long long A[2][2];
            A[0][0] = 0ull; A[0][1] = 0ull; A[1][0] = 0ull; A[1][1] = 0ull;
            mv2(sm.Wx1g, &sm.h0f[(2 * bp) * HR], kbase, quad, A);
            float4 S1v = *reinterpret_cast<const float4*>(&sm.S1cs[ks][lcq]);
            unsigned long long S1a = pack2(S1v.x, S1v.y);
            unsigned long long S1b = pack2(S1v.z, S1v.w);
            #pragma unroll
            for (int d = 0; d < 2; ++d) {
                int b = 2 * bp + d;
                float s4 = sm.red2[b].x + sm.red2[8 + b].x + sm.red2[16 + b].x + sm.red2[24 + b].x;
                float q4 = sm.red2[b].y + sm.red2[8 + b].y + sm.red2[16 + b].y + sm.red2[24 + b].y;
                float mu  = s4 * (1.0f / 128.0f);
                float var = fmaxf(q4 * (1.0f / 128.0f) - mu * mu, 0.0f);
                float rs  = rsqrtf(var + LN_EPS_);
                float rm  = -rs * mu;
                unsigned long long rs2 = pack2(rs, rs);
                unsigned long long rm2 = pack2(rm, rm);
                unsigned long long zw0 = *reinterpret_cast<unsigned long long*>(zp1 + d * 128);
                unsigned long long zw1 = *reinterpret_cast<unsigned long long*>(zp1 + d * 128 + 2);
                fma2p(zw0, rs2, A[0][d]); fma2p(zw0, rm2, S1a);
                fma2p(zw1, rs2, A[1][d]); fma2p(zw1, rm2, S1b);
                *reinterpret_cast<unsigned long long*>(zp1 + d * 128)     = zw0;
                *reinterpret_cast<unsigned long long*>(zp1 + d * 128 + 2) = zw1;
            }
        } else {
            // local FC + softmax for step t-1 (warps 8/9, one batch each)
            if (w8 < 2 && t > 0) {
                int bown = (int)rank * 2 + w8;
                fc_softmax(&sm.hs[w8 * 128], sm.WfcT, sm.bfcs,
                           out + ((size_t)(bstart + bown) * TT + (t - 1)) * NC,
                           tid & 31);
            }
            // x/t prefetch for t+2 (warp 10)
            if (t + 2 < TT) {
                if (tid >= 320 && tid < 320 + GC)
                    sm.tmb[par][tid - 320] = times[(size_t)(bstart + (tid - 320)) * TT + t + 2];
                if (tid >= 328 && tid < 328 + GC * NF) {
                    int ii = tid - 328;
                    int g = ii / NF, f = ii - g * NF;
                    sm.xb[par][g][f] = inputs[((size_t)(bstart + g) * TT + t + 2) * NF + f];
                }
            }
            // next z0 = x(t+1)@Wx0 + Wh0@h0(t) + b0 (A reads it next iter, after S2)
            if (t + 1 < TT) {
                unsigned long long acc0[2][2];
                if (ks == 0) {
                    float4 w0v = *reinterpret_cast<const float4*>(&sm.Wx0s[lcq]);
                    float4 w1v = *reinterpret_cast<const float4*>(&sm.Wx0s[128 + lcq]);
                    float4 w2v = *reinterpret_cast<const float4*>(&sm.Wx0s[256 + lcq]);
                    float4 w3v = *reinterpret_cast<const float4*>(&sm.Wx0s[384 + lcq]);
                    #pragma unroll
                    for (int d = 0; d < 2; ++d) {
                        const float* x = sm.xb[parn][2 * bp + d];
                        float xa = x[0], xb_ = x[1], xc = x[2];
                        float v0 = w3v.x + xa * w0v.x + xb_ * w1v.x + xc * w2v.x;
                        float v1 = w3v.y + xa * w0v.y + xb_ * w1v.y + xc * w2v.y;
                        float v2 = w3v.z + xa * w0v.z + xb_ * w1v.z + xc * w2v.z;
                        float v3 = w3v.w + xa * w0v.w + xb_ * w1v.w + xc * w2v.w;
                        acc0[0][d] = pack2(v0, v1);
                        acc0[1][d] = pack2(v2, v3);
                    }
                } else {
                    acc0[0][0] = 0ull; acc0[0][1] = 0ull;
                    acc0[1][0] = 0ull; acc0[1][1] = 0ull;
                }
                mv2(sm.Wh0s, &sm.h0f[(2 * bp) * HR], kbase, quad, acc0);
                *reinterpret_cast<unsigned long long*>(zp0)       = acc0[0][0];
                *reinterpret_cast<unsigned long long*>(zp0 + 2)   = acc0[1][0];
                *reinterpret_cast<unsigned long long*>(zp0 + 128) = acc0[0][1];
                *reinterpret_cast<unsigned long long*>(zp0 + 130) = acc0[1][1];
            }
        }
        __syncthreads();                       // B3: z1 ready

        // ===== P3: A: gates1 + packed h1 exchange | B: straight to S2 =====
        if (isA) {
            const float* zb = sm.z1 + gb * 128;
            float zi = zb[gj]      + zb[1024 + gj];
            float zf = zb[32 + gj] + zb[1024 + 32 + gj];
            float zg = zb[64 + gj] + zb[1024 + 64 + gj];
            float zo = zb[96 + gj] + zb[1024 + 96 + gj];
            plstm_gate2(zi, zf, zg, zo, tcur, rtau1, ritau1, rs1, h1own, c1own);
            float v0 = __shfl_sync(0xffffffffu, h1own, packsrc + 0);
            float v1 = __shfl_sync(0xffffffffu, h1own, packsrc + 1);
            float v2 = __shfl_sync(0xffffffffu, h1own, packsrc + 2);
            float v3 = __shfl_sync(0xffffffffu, h1own, packsrc + 3);
            uint32_t la = (uint32_t)__cvta_generic_to_shared(
                &sm.h1f[gb * HR + (int)rank * OWN + packsrc]);
            stc_v4(la, dstrank, v0, v1, v2, v3);
        }
        CLUSTER_SYNC();        // S2: h1(t) visible; z1/h0f free for next step
    }

    // ===== epilogue: FC + softmax for the final step (TT-1), h1f is final =====
    if (!isA && w8 < 2) {
        int bown = (int)rank * 2 + w8;
        fc_softmax(&sm.h1f[bown * HR], sm.WfcT, sm.bfcs,
                   out + ((size_t)(bstart + bown) * TT + (TT - 1)) * NC,
                   tid & 31);
    }
}

extern "C" void kernel_launch(void* const* d_in, const int* in_sizes, int n_in,
                              void* d_out, int out_size) {
    const float* inputs = (const float*)d_in[0];
    const float* times  = (const float*)d_in[1];
    const float* Wx0    = (const float*)d_in[2];
    const float* Wh0    = (const float*)d_in[3];
    const float* b0     = (const float*)d_in[4];
    const float* tau0   = (const float*)d_in[5];
    const float* s0     = (const float*)d_in[6];
    const float* Wx1    = (const float*)d_in[7];
    const float* Wh1    = (const float*)d_in[8];
    const float* b1     = (const float*)d_in[9];
    const float* tau1   = (const float*)d_in[10];
    const float* s1     = (const float*)d_in[11];
    const float* gamma  = (const float*)d_in[12];
    const float* beta   = (const float*)d_in[13];
    const float* Wfc    = (const float*)d_in[14];
    const float* bfc    = (const float*)d_in[15];

    cudaFuncSetAttribute(plstm_cluster_kernel,
                         cudaFuncAttributeMaxDynamicSharedMemorySize,
                         (int)sizeof(SM));
    plstm_cluster_kernel<<<NCTA, NTHR, sizeof(SM)>>>(
        inputs, times, Wx0, Wh0, b0, tau0, s0,
        Wx1, Wh1, b1, tau1, s1, gamma, beta, Wfc, bfc, (float*)d_out);
}